// round 6
// baseline (speedup 1.0000x reference)
#include <cuda_runtime.h>

// Polar decomposition of A = rotation[n] @ mat. 2 matrices/thread packed in
// f32x2 (FFMA2), smem-staged coalesced I/O. MUFU-free:
//  head:  det-scaled Newton X <- 0.5*g*X + 0.5*g^2*sign(det)*cof(X),
//         g = |det|^(-1/3) via bit-trick + 1 Newton polish (all FMA).
//  tail:  Newton-Schulz X <- X(3I - X^T X)/2, guard tr(X^T X) < 4.5,
//         exit when |tr - 3| < 3e-4 (final steps are provably NS).

#define TPB 256
typedef unsigned long long u64;

__device__ __forceinline__ u64 f2pack(float lo, float hi) {
    u64 r; asm("mov.b64 %0, {%1, %2};" : "=l"(r) : "f"(lo), "f"(hi)); return r;
}
__device__ __forceinline__ void f2unpack(u64 v, float& lo, float& hi) {
    asm("mov.b64 {%0, %1}, %2;" : "=f"(lo), "=f"(hi) : "l"(v));
}
__device__ __forceinline__ u64 f2mul(u64 a, u64 b) {
    u64 d; asm("mul.rn.f32x2 %0, %1, %2;" : "=l"(d) : "l"(a), "l"(b)); return d;
}
__device__ __forceinline__ u64 f2add(u64 a, u64 b) {
    u64 d; asm("add.rn.f32x2 %0, %1, %2;" : "=l"(d) : "l"(a), "l"(b)); return d;
}
__device__ __forceinline__ u64 f2fma(u64 a, u64 b, u64 c) {
    u64 d; asm("fma.rn.f32x2 %0, %1, %2, %3;" : "=l"(d) : "l"(a), "l"(b), "l"(c)); return d;
}
__device__ __forceinline__ u64 f2neg(u64 a) { return a ^ 0x8000000080000000ULL; }
__device__ __forceinline__ u64 f2msub(u64 a, u64 b, u64 c, u64 d) {
    return f2fma(a, b, f2neg(f2mul(c, d)));
}

// |x|^(-1/3) for x > 0, ~1e-3 rel error after one polish (all fixed-latency ops)
__device__ __forceinline__ float invcbrt_fast(float x) {
    int i = __float_as_int(x);
    i = 0x54A2FA8C - i / 3;
    float y = __int_as_float(i);
    const float y3 = y * y * y;
    y = y * 0.33333333f * fmaf(-x, y3, 4.0f);   // y*(4 - x*y^3)/3
    return y;
}

struct P2 { u64 x0,x1,x2,x3,x4,x5,x6,x7,x8; };

// One det-scaled Newton step (rcp-free, MUFU-free).
__device__ __forceinline__ void newton_step(P2& X) {
    const u64 c00 = f2msub(X.x4, X.x8, X.x5, X.x7);
    const u64 c01 = f2msub(X.x5, X.x6, X.x3, X.x8);
    const u64 c02 = f2msub(X.x3, X.x7, X.x4, X.x6);
    const u64 c10 = f2msub(X.x2, X.x7, X.x1, X.x8);
    const u64 c11 = f2msub(X.x0, X.x8, X.x2, X.x6);
    const u64 c12 = f2msub(X.x1, X.x6, X.x0, X.x7);
    const u64 c20 = f2msub(X.x1, X.x5, X.x2, X.x4);
    const u64 c21 = f2msub(X.x2, X.x3, X.x0, X.x5);
    const u64 c22 = f2msub(X.x0, X.x4, X.x1, X.x3);
    const u64 det = f2fma(X.x0, c00, f2fma(X.x1, c01, f2mul(X.x2, c02)));

    float dl, dh;
    f2unpack(det, dl, dh);
    const float gl = invcbrt_fast(fmaxf(fabsf(dl), 1e-30f));
    const float gh = invcbrt_fast(fmaxf(fabsf(dh), 1e-30f));
    const float rl = copysignf(0.5f * gl * gl, dl);   // ~0.5/(g*det)
    const float rh = copysignf(0.5f * gh * gh, dh);
    const u64 hg = f2pack(0.5f * gl, 0.5f * gh);
    const u64 rr = f2pack(rl, rh);

    X.x0 = f2fma(rr, c00, f2mul(hg, X.x0));
    X.x1 = f2fma(rr, c01, f2mul(hg, X.x1));
    X.x2 = f2fma(rr, c02, f2mul(hg, X.x2));
    X.x3 = f2fma(rr, c10, f2mul(hg, X.x3));
    X.x4 = f2fma(rr, c11, f2mul(hg, X.x4));
    X.x5 = f2fma(rr, c12, f2mul(hg, X.x5));
    X.x6 = f2fma(rr, c20, f2mul(hg, X.x6));
    X.x7 = f2fma(rr, c21, f2mul(hg, X.x7));
    X.x8 = f2fma(rr, c22, f2mul(hg, X.x8));
}

__device__ __forceinline__ void gram(const P2& X, u64 B[6], u64& tr) {
    B[0] = f2fma(X.x0, X.x0, f2fma(X.x3, X.x3, f2mul(X.x6, X.x6)));
    B[1] = f2fma(X.x0, X.x1, f2fma(X.x3, X.x4, f2mul(X.x6, X.x7)));
    B[2] = f2fma(X.x0, X.x2, f2fma(X.x3, X.x5, f2mul(X.x6, X.x8)));
    B[3] = f2fma(X.x1, X.x1, f2fma(X.x4, X.x4, f2mul(X.x7, X.x7)));
    B[4] = f2fma(X.x1, X.x2, f2fma(X.x4, X.x5, f2mul(X.x7, X.x8)));
    B[5] = f2fma(X.x2, X.x2, f2fma(X.x5, X.x5, f2mul(X.x8, X.x8)));
    tr = f2add(B[0], f2add(B[3], B[5]));
}

// X <- X @ (1.5 I - 0.5 B), B = X^T X symmetric.
__device__ __forceinline__ void ns_update(P2& X, const u64 B[6]) {
    const u64 c15  = f2pack(1.5f, 1.5f);
    const u64 cm05 = f2pack(-0.5f, -0.5f);
    const u64 p00 = f2fma(B[0], cm05, c15);
    const u64 p01 = f2mul(B[1], cm05);
    const u64 p02 = f2mul(B[2], cm05);
    const u64 p11 = f2fma(B[3], cm05, c15);
    const u64 p12 = f2mul(B[4], cm05);
    const u64 p22 = f2fma(B[5], cm05, c15);

    const u64 y0 = f2fma(X.x0, p00, f2fma(X.x1, p01, f2mul(X.x2, p02)));
    const u64 y1 = f2fma(X.x0, p01, f2fma(X.x1, p11, f2mul(X.x2, p12)));
    const u64 y2 = f2fma(X.x0, p02, f2fma(X.x1, p12, f2mul(X.x2, p22)));
    const u64 y3 = f2fma(X.x3, p00, f2fma(X.x4, p01, f2mul(X.x5, p02)));
    const u64 y4 = f2fma(X.x3, p01, f2fma(X.x4, p11, f2mul(X.x5, p12)));
    const u64 y5 = f2fma(X.x3, p02, f2fma(X.x4, p12, f2mul(X.x5, p22)));
    const u64 y6 = f2fma(X.x6, p00, f2fma(X.x7, p01, f2mul(X.x8, p02)));
    const u64 y7 = f2fma(X.x6, p01, f2fma(X.x7, p11, f2mul(X.x8, p12)));
    const u64 y8 = f2fma(X.x6, p02, f2fma(X.x7, p12, f2mul(X.x8, p22)));
    X.x0 = y0; X.x1 = y1; X.x2 = y2;
    X.x3 = y3; X.x4 = y4; X.x5 = y5;
    X.x6 = y6; X.x7 = y7; X.x8 = y8;
}

__global__ void __launch_bounds__(TPB)
polar2f_kernel(const float* __restrict__ rot,
               const float* __restrict__ mat,
               float* __restrict__ out,
               float* __restrict__ logdet,
               int N)
{
    __shared__ float s[TPB * 18];
    const int tid  = threadIdx.x;
    const int base = blockIdx.x * (TPB * 2);
    const int nmat = min(TPB * 2, N - base);
    const int nflt = nmat * 9;

    // ---- cooperative coalesced load: global -> smem ----
    {
        const float* g = rot + (size_t)base * 9;
        const int nv = nflt >> 2;
        const float4* g4 = reinterpret_cast<const float4*>(g);
        float4* s4 = reinterpret_cast<float4*>(s);
        for (int i = tid; i < nv; i += TPB) s4[i] = g4[i];
        for (int i = (nv << 2) + tid; i < nflt; i += TPB) s[i] = g[i];
    }

    const float m0 = __ldg(mat + 0), m1 = __ldg(mat + 1), m2 = __ldg(mat + 2);
    const float m3 = __ldg(mat + 3), m4 = __ldg(mat + 4), m5 = __ldg(mat + 5);
    const float m6 = __ldg(mat + 6), m7 = __ldg(mat + 7), m8 = __ldg(mat + 8);
    __syncthreads();

    const bool vlo = (base + 2 * tid)     < N;
    const bool vhi = (base + 2 * tid + 1) < N;

    u64 R[9];
    {
        const int olo = 2 * tid * 9, ohi = olo + 9;
        #pragma unroll
        for (int k = 0; k < 9; ++k) {
            const float idv = (k == 0 || k == 4 || k == 8) ? 1.0f : 0.0f;
            const float a = vlo ? s[olo + k] : idv;
            const float b = vhi ? s[ohi + k] : idv;
            R[k] = f2pack(a, b);
        }
    }
    __syncthreads();

    const u64 M0 = f2pack(m0, m0), M1 = f2pack(m1, m1), M2 = f2pack(m2, m2);
    const u64 M3 = f2pack(m3, m3), M4 = f2pack(m4, m4), M5 = f2pack(m5, m5);
    const u64 M6 = f2pack(m6, m6), M7 = f2pack(m7, m7), M8 = f2pack(m8, m8);

    P2 X;
    X.x0 = f2fma(R[0], M0, f2fma(R[1], M3, f2mul(R[2], M6)));
    X.x1 = f2fma(R[0], M1, f2fma(R[1], M4, f2mul(R[2], M7)));
    X.x2 = f2fma(R[0], M2, f2fma(R[1], M5, f2mul(R[2], M8)));
    X.x3 = f2fma(R[3], M0, f2fma(R[4], M3, f2mul(R[5], M6)));
    X.x4 = f2fma(R[3], M1, f2fma(R[4], M4, f2mul(R[5], M7)));
    X.x5 = f2fma(R[3], M2, f2fma(R[4], M5, f2mul(R[5], M8)));
    X.x6 = f2fma(R[6], M0, f2fma(R[7], M3, f2mul(R[8], M6)));
    X.x7 = f2fma(R[6], M1, f2fma(R[7], M4, f2mul(R[8], M7)));
    X.x8 = f2fma(R[6], M2, f2fma(R[7], M5, f2mul(R[8], M8)));

    // ---- head: 3 det-scaled steps, no checks ----
    #pragma unroll
    for (int it = 0; it < 3; ++it) newton_step(X);

    // ---- adaptive tail: NS when safe, else another scaled step ----
    #pragma unroll 1
    for (int it = 0; it < 10; ++it) {
        u64 B[6], tr;
        gram(X, B, tr);
        float t0, t1;
        f2unpack(tr, t0, t1);
        const float err = fmaxf(fabsf(t0 - 3.0f), fabsf(t1 - 3.0f));
        if (__all_sync(0xffffffffu, err < 3e-4f)) break;
        if (__all_sync(0xffffffffu, fmaxf(t0, t1) < 4.5f)) {
            ns_update(X, B);
        } else {
            newton_step(X);
        }
    }

    // ---- scatter to smem, cooperative coalesced store ----
    {
        const int olo = 2 * tid * 9, ohi = olo + 9;
        float a, b;
        f2unpack(X.x0, a, b); s[olo + 0] = a; s[ohi + 0] = b;
        f2unpack(X.x1, a, b); s[olo + 1] = a; s[ohi + 1] = b;
        f2unpack(X.x2, a, b); s[olo + 2] = a; s[ohi + 2] = b;
        f2unpack(X.x3, a, b); s[olo + 3] = a; s[ohi + 3] = b;
        f2unpack(X.x4, a, b); s[olo + 4] = a; s[ohi + 4] = b;
        f2unpack(X.x5, a, b); s[olo + 5] = a; s[ohi + 5] = b;
        f2unpack(X.x6, a, b); s[olo + 6] = a; s[ohi + 6] = b;
        f2unpack(X.x7, a, b); s[olo + 7] = a; s[ohi + 7] = b;
        f2unpack(X.x8, a, b); s[olo + 8] = a; s[ohi + 8] = b;
    }
    __syncthreads();
    {
        float* g = out + (size_t)base * 9;
        const int nv = nflt >> 2;
        const float4* s4 = reinterpret_cast<const float4*>(s);
        float4* g4 = reinterpret_cast<float4*>(g);
        for (int i = tid; i < nv; i += TPB) g4[i] = s4[i];
        for (int i = (nv << 2) + tid; i < nflt; i += TPB) g[i] = s[i];
    }

    for (int i = tid; i < nmat; i += TPB) logdet[base + i] = 0.0f;
}

__global__ void zero_tail_kernel(float* __restrict__ p, long long n)
{
    long long i = (long long)blockIdx.x * blockDim.x + threadIdx.x;
    if (i < n) p[i] = 0.0f;
}

extern "C" void kernel_launch(void* const* d_in, const int* in_sizes, int n_in,
                              void* d_out, int out_size)
{
    const float* rot = (const float*)d_in[0];
    const float* mat = (const float*)d_in[1];
    float* out = (float*)d_out;

    const int N = in_sizes[0] / 9;
    float* logdet = out + (size_t)N * 9;

    const int mats_per_block = TPB * 2;
    const int blocks = (N + mats_per_block - 1) / mats_per_block;
    polar2f_kernel<<<blocks, TPB>>>(rot, mat, out, logdet, N);

    const long long used = 10LL * N;
    if ((long long)out_size > used) {
        const long long extra = (long long)out_size - used;
        const int zb = (int)((extra + 255) / 256);
        zero_tail_kernel<<<zb, 256>>>(out + used, extra);
    }
}